// round 14
// baseline (speedup 1.0000x reference)
#include <cuda_runtime.h>
#include <cuda_bf16.h>
#include <cstddef>
#include <cstdint>

// Problem constants
#define Bq  2
#define Sq  2048
#define Hq  2048
#define NHq 32
#define HDq 64

// fp32 scratch
__device__ float    g_Q[Bq * Sq * Hq];
__device__ float    g_K[Bq * Sq * Hq];
__device__ float    g_V[Bq * Sq * Hq];
// Packed bf16 hi/lo planes (2 bf16 per uint32, packed along K/k-dim)
__device__ uint32_t g_Wh[4][Hq * Hq / 2];
__device__ uint32_t g_Wl[4][Hq * Hq / 2];
__device__ uint32_t g_Xh[Bq * Sq * Hq / 2];
__device__ uint32_t g_Xl[Bq * Sq * Hq / 2];
__device__ uint32_t g_Kph[Bq * Sq * Hq / 2];
__device__ uint32_t g_Kpl[Bq * Sq * Hq / 2];
// V transposed-packed: [(b*NH+h)*64 + d][Sq/2] words, word = (V[2s],V[2s+1])
__device__ uint32_t g_Vth[Bq * NHq * HDq * Sq / 2];
__device__ uint32_t g_Vtl[Bq * NHq * HDq * Sq / 2];
// Attention output packed planes [m][Hq/2]
__device__ uint32_t g_Aph[Bq * Sq * Hq / 2];
__device__ uint32_t g_Apl[Bq * Sq * Hq / 2];

// ---------------------------------------------------------------------------
// Helpers
// ---------------------------------------------------------------------------
__device__ __forceinline__ uint32_t bf16x2_pack(float hi_elem, float lo_elem) {
    uint32_t r;
    asm("cvt.rn.bf16x2.f32 %0, %1, %2;" : "=r"(r) : "f"(hi_elem), "f"(lo_elem));
    return r;
}
__device__ __forceinline__ float bfu_lo(uint32_t w) {
    return __uint_as_float(w << 16);
}
__device__ __forceinline__ float bfu_hi(uint32_t w) {
    return __uint_as_float(w & 0xFFFF0000u);
}

__device__ __forceinline__ void mma_bf16(float c[4], const uint32_t a[4],
                                         const uint32_t b[2]) {
    asm volatile(
        "mma.sync.aligned.m16n8k16.row.col.f32.bf16.bf16.f32 "
        "{%0,%1,%2,%3}, {%4,%5,%6,%7}, {%8,%9}, {%0,%1,%2,%3};\n"
        : "+f"(c[0]), "+f"(c[1]), "+f"(c[2]), "+f"(c[3])
        : "r"(a[0]), "r"(a[1]), "r"(a[2]), "r"(a[3]), "r"(b[0]), "r"(b[1]));
}

#define FROT(m) ((((m) >> 1) & 3) << 2)

// ---------------------------------------------------------------------------
// Generic pre-pass: split fp32 -> packed bf16 hi/lo planes.
// ---------------------------------------------------------------------------
__device__ __forceinline__ void split4(float4 v, uint2& h, uint2& l) {
    uint32_t h0 = bf16x2_pack(v.y, v.x);
    uint32_t h1 = bf16x2_pack(v.w, v.z);
    float r0 = v.x - bfu_lo(h0);
    float r1 = v.y - bfu_hi(h0);
    float r2 = v.z - bfu_lo(h1);
    float r3 = v.w - bfu_hi(h1);
    h = make_uint2(h0, h1);
    l = make_uint2(bf16x2_pack(r1, r0), bf16x2_pack(r3, r2));
}

__global__ void split_pack(const float4* __restrict__ src,
                           uint2* __restrict__ dh, uint2* __restrict__ dl,
                           int n4) {
    int i = blockIdx.x * blockDim.x + threadIdx.x;
    if (i >= n4) return;
    uint2 h, l;
    split4(src[i], h, l);
    dh[i] = h;
    dl[i] = l;
}

__global__ void split_w_bf16(const float4* __restrict__ w0,
                             const float4* __restrict__ w1,
                             const float4* __restrict__ w2,
                             const float4* __restrict__ w3, int n4) {
    int i = blockIdx.x * blockDim.x + threadIdx.x;
    if (i >= n4) return;
    const float4* s = (blockIdx.y == 0) ? w0 : (blockIdx.y == 1) ? w1
                      : (blockIdx.y == 2) ? w2 : w3;
    uint2 h, l;
    split4(s[i], h, l);
    ((uint2*)g_Wh[blockIdx.y])[i] = h;
    ((uint2*)g_Wl[blockIdx.y])[i] = l;
}

// ---------------------------------------------------------------------------
// V transpose-pack: per (b,h) 64-row tile, write [d][s/2] packed planes.
// ---------------------------------------------------------------------------
__global__ void vtrans_pack(const float* __restrict__ V) {
    __shared__ float vt[64][65];
    const int tid = threadIdx.x;
    const int bh  = blockIdx.y;
    const int b   = bh >> 5;
    const int h   = bh & 31;
    const int s0  = blockIdx.x * 64;

    const float* Vb = V + (size_t)(b * Sq + s0) * Hq + h * 64;
#pragma unroll
    for (int it = 0; it < 4; ++it) {
        int f = tid + it * 256;
        int s = f >> 4, d0 = (f & 15) << 2;
        float4 v = *(const float4*)(Vb + (size_t)s * Hq + d0);
        vt[s][d0] = v.x; vt[s][d0 + 1] = v.y;
        vt[s][d0 + 2] = v.z; vt[s][d0 + 3] = v.w;
    }
    __syncthreads();

    const int d  = tid >> 2;
    const int w0 = (tid & 3) << 3;
    uint32_t hw[8], lw[8];
#pragma unroll
    for (int j = 0; j < 8; ++j) {
        int s2 = w0 + j;
        float a0 = vt[2 * s2][d], a1 = vt[2 * s2 + 1][d];
        uint32_t hv = bf16x2_pack(a1, a0);
        float r0 = a0 - bfu_lo(hv);
        float r1 = a1 - bfu_hi(hv);
        hw[j] = hv;
        lw[j] = bf16x2_pack(r1, r0);
    }
    size_t base = ((size_t)(bh * 64 + d)) * (Sq / 2) + (s0 >> 1) + w0;
    *(uint4*)&g_Vth[base]     = make_uint4(hw[0], hw[1], hw[2], hw[3]);
    *(uint4*)&g_Vth[base + 4] = make_uint4(hw[4], hw[5], hw[6], hw[7]);
    *(uint4*)&g_Vtl[base]     = make_uint4(lw[0], lw[1], lw[2], lw[3]);
    *(uint4*)&g_Vtl[base + 4] = make_uint4(lw[4], lw[5], lw[6], lw[7]);
}

// ---------------------------------------------------------------------------
// bf16 3-mma GEMM (NT), both operands pre-split packed planes.
// Block tile 128x128, K-chunk 32 (16 words), 256 thr, warp tile 64x32.
// ---------------------------------------------------------------------------
#define GP 2048   // words per smem plane (128*16)

__device__ __forceinline__ void gemm_bf3_core(uint32_t* sm,
        const uint32_t* __restrict__ Ahg0, const uint32_t* __restrict__ Alg0,
        const uint32_t* __restrict__ Bhg0, const uint32_t* __restrict__ Blg0,
        float* __restrict__ C, int M, int N, int K, int m0, int n0) {
    uint32_t* Ah = sm;
    uint32_t* Al = sm + GP;
    uint32_t* Bh = sm + 2 * GP;
    uint32_t* Bl = sm + 3 * GP;

    const int tid  = threadIdx.x;
    const int lane = tid & 31;
    const int wid  = tid >> 5;
    const int wm   = (wid & 1) * 64;
    const int wn   = (wid >> 1) * 32;
    const int g    = lane >> 2;
    const int tig  = lane & 3;

    const int row = tid >> 1;
    const int hb  = tid & 1;
    const int fr  = FROT(row);
    const int KW  = K >> 1;

    const uint32_t* Ahg = Ahg0 + (size_t)(m0 + row) * KW + 8 * hb;
    const uint32_t* Alg = Alg0 + (size_t)(m0 + row) * KW + 8 * hb;
    const uint32_t* Bhg = Bhg0 + (size_t)(n0 + row) * KW + 8 * hb;
    const uint32_t* Blg = Blg0 + (size_t)(n0 + row) * KW + 8 * hb;

    float acc[4][4][4];
#pragma unroll
    for (int i = 0; i < 4; ++i)
#pragma unroll
        for (int j = 0; j < 4; ++j)
#pragma unroll
            for (int r = 0; r < 4; ++r) acc[i][j][r] = 0.0f;

    uint4 pah[2], pal[2], pbh[2], pbl[2];
#pragma unroll
    for (int v = 0; v < 2; ++v) {
        pah[v] = *(const uint4*)(Ahg + 4 * v);
        pal[v] = *(const uint4*)(Alg + 4 * v);
        pbh[v] = *(const uint4*)(Bhg + 4 * v);
        pbl[v] = *(const uint4*)(Blg + 4 * v);
    }

    const int NCH = K >> 5;
    for (int ch = 0; ch < NCH; ++ch) {
#pragma unroll
        for (int v = 0; v < 2; ++v) {
            int col = (8 * hb + 4 * v) ^ fr;
            *(uint4*)&Ah[row * 16 + col] = pah[v];
            *(uint4*)&Al[row * 16 + col] = pal[v];
            *(uint4*)&Bh[row * 16 + col] = pbh[v];
            *(uint4*)&Bl[row * 16 + col] = pbl[v];
        }
        __syncthreads();

        if (ch + 1 < NCH) {
            const uint32_t* Ahp = Ahg + (size_t)(ch + 1) * 16;
            const uint32_t* Alp = Alg + (size_t)(ch + 1) * 16;
            const uint32_t* Bhp = Bhg + (size_t)(ch + 1) * 16;
            const uint32_t* Blp = Blg + (size_t)(ch + 1) * 16;
#pragma unroll
            for (int v = 0; v < 2; ++v) {
                pah[v] = *(const uint4*)(Ahp + 4 * v);
                pal[v] = *(const uint4*)(Alp + 4 * v);
                pbh[v] = *(const uint4*)(Bhp + 4 * v);
                pbl[v] = *(const uint4*)(Blp + 4 * v);
            }
        }

#pragma unroll
        for (int ks = 0; ks < 2; ++ks) {
            const int kc = tig + 8 * ks;

            uint32_t ah[4][4], al[4][4];
#pragma unroll
            for (int ma = 0; ma < 4; ++ma) {
                int m = wm + ma * 16 + g;
                int off = m * 16 + (kc ^ FROT(m));
                ah[ma][0] = Ah[off];
                ah[ma][1] = Ah[off + 128];
                ah[ma][2] = Ah[off ^ 4];
                ah[ma][3] = Ah[(off ^ 4) + 128];
                al[ma][0] = Al[off];
                al[ma][1] = Al[off + 128];
                al[ma][2] = Al[off ^ 4];
                al[ma][3] = Al[(off ^ 4) + 128];
            }
#pragma unroll
            for (int na = 0; na < 4; ++na) {
                int n = wn + na * 8 + g;
                int offb = n * 16 + (kc ^ FROT(n));
                uint32_t bh[2], bl[2];
                bh[0] = Bh[offb];
                bh[1] = Bh[offb ^ 4];
                bl[0] = Bl[offb];
                bl[1] = Bl[offb ^ 4];
#pragma unroll
                for (int ma = 0; ma < 4; ++ma) {
                    mma_bf16(acc[ma][na], ah[ma], bh);
                    mma_bf16(acc[ma][na], al[ma], bh);
                    mma_bf16(acc[ma][na], ah[ma], bl);
                }
            }
        }
        __syncthreads();
    }

#pragma unroll
    for (int ma = 0; ma < 4; ++ma) {
        int r0 = m0 + wm + ma * 16 + g;
#pragma unroll
        for (int na = 0; na < 4; ++na) {
            int c = n0 + wn + na * 8 + 2 * tig;
            *(float2*)&C[(size_t)r0 * N + c] =
                make_float2(acc[ma][na][0], acc[ma][na][1]);
            *(float2*)&C[(size_t)(r0 + 8) * N + c] =
                make_float2(acc[ma][na][2], acc[ma][na][3]);
        }
    }
}

__global__ void gemm_bf3_o(float* __restrict__ C) {
    extern __shared__ uint32_t smg[];
    gemm_bf3_core(smg, g_Aph, g_Apl, g_Wh[3], g_Wl[3], C, Bq * Sq, Hq, Hq,
                  blockIdx.y * 128, blockIdx.x * 128);
}

__global__ void gemm_bf3_qkv(float* __restrict__ Qo, float* __restrict__ Ko,
                             float* __restrict__ Vo) {
    extern __shared__ uint32_t smg[];
    const int which = blockIdx.x >> 4;
    float* C = (which == 0) ? Qo : (which == 1) ? Ko : Vo;
    gemm_bf3_core(smg, g_Xh, g_Xl, g_Wh[which], g_Wl[which], C,
                  Bq * Sq, Hq, Hq, blockIdx.y * 128, (blockIdx.x & 15) * 128);
}

// ---------------------------------------------------------------------------
// RoPE (in-place) on Q and K. Q also folded with 1/sqrt(HD) = 0.125.
// ---------------------------------------------------------------------------
__global__ void rope_kernel(float* __restrict__ Q, float* __restrict__ K,
                            const float* __restrict__ cs,
                            const float* __restrict__ sn) {
    const int PAIRS = Bq * Sq * NHq * (HDq / 2);
    int idx = blockIdx.x * blockDim.x + threadIdx.x;
    if (idx >= 2 * PAIRS) return;
    bool isQ = idx < PAIRS;
    int p = isQ ? idx : idx - PAIRS;

    int d = p & 31;
    int h = (p >> 5) & 31;
    int s = (p >> 10) & 2047;
    int b = p >> 21;

    size_t base = ((size_t)(b * Sq + s) * Hq) + (size_t)h * HDq + d;
    float c1 = cs[s * HDq + d],      s1 = sn[s * HDq + d];
    float c2 = cs[s * HDq + d + 32], s2 = sn[s * HDq + d + 32];

    float* T = isQ ? Q : K;
    float scale = isQ ? 0.125f : 1.0f;
    float x1 = T[base];
    float x2 = T[base + 32];
    T[base]      = (x1 * c1 - x2 * s1) * scale;
    T[base + 32] = (x2 * c2 + x1 * s2) * scale;
}

// ---------------------------------------------------------------------------
// Flash attention, bf16 3-mma; K/V arrive pre-split+pre-packed, Q in regs,
// P in regs. Per-tile loads are pure uint4 copies. Output -> packed planes.
// ---------------------------------------------------------------------------
__global__ __launch_bounds__(256, 2)
void attn_bf16(const float* __restrict__ Q, const float* __restrict__ mask) {
    __shared__ uint32_t Kh[2048], Kl[2048], Vh[2048], Vl[2048];
    __shared__ float msk[64];

    const int tid  = threadIdx.x;
    const int lane = tid & 31;
    const int wid  = tid >> 5;
    const int g    = lane >> 2;
    const int tig  = lane & 3;
    const int R    = wid * 16 + g;
    const int R8   = R + 8;
    const int g4   = g << 2;

    const int b  = blockIdx.z;
    const int h  = blockIdx.y;
    const int q0 = blockIdx.x * 128;
    const size_t ho = (size_t)h * HDq;

    // Loader indices (shared by K and V tiles)
    const int lr = tid >> 2;             // 0..63 (K: kv row / V: d row)
    const int w0 = (tid & 3) << 3;       // 0,8,16,24
    const int lrot = (lr & 7) << 2;
    const int c1 = w0 ^ lrot;
    const int c2 = (w0 + 4) ^ lrot;

    // ---- Q rows -> registers, packed bf16 hi/lo ----
    uint32_t qh[2][8], ql[2][8];
    {
        const float* Qb = Q + ((size_t)(b * Sq + q0) * Hq) + ho;
#pragma unroll
        for (int rr = 0; rr < 2; ++rr) {
            const float* Qr = Qb + (size_t)(rr ? R8 : R) * Hq + 2 * tig;
#pragma unroll
            for (int u = 0; u < 8; ++u) {
                float2 q = *(const float2*)(Qr + 8 * u);
                uint32_t hw = bf16x2_pack(q.y, q.x);
                float r0 = q.x - bfu_lo(hw);
                float r1 = q.y - bfu_hi(hw);
                qh[rr][u] = hw;
                ql[rr][u] = bf16x2_pack(r1, r0);
            }
        }
    }

    float o[8][4];
#pragma unroll
    for (int na = 0; na < 8; ++na)
#pragma unroll
        for (int e = 0; e < 4; ++e) o[na][e] = 0.0f;
    float mrow[2] = {-1e30f, -1e30f};
    float lrow[2] = {0.0f, 0.0f};

    const size_t vrow = ((size_t)((b * NHq + h) * HDq + lr)) * (Sq / 2) + w0;

    for (int t = 0; t < Sq / 64; ++t) {
        const int c0 = t * 64;

        // ---- K tile copy (packed planes) ----
        {
            size_t gb = (((size_t)(b * Sq + c0 + lr) * Hq) + ho) >> 1;
            *(uint4*)&Kh[lr * 32 + c1] = *(const uint4*)&g_Kph[gb + w0];
            *(uint4*)&Kh[lr * 32 + c2] = *(const uint4*)&g_Kph[gb + w0 + 4];
            *(uint4*)&Kl[lr * 32 + c1] = *(const uint4*)&g_Kpl[gb + w0];
            *(uint4*)&Kl[lr * 32 + c2] = *(const uint4*)&g_Kpl[gb + w0 + 4];
        }
        // ---- V tile copy (transposed-packed planes) ----
        {
            size_t gb = vrow + (size_t)(c0 >> 1);
            *(uint4*)&Vh[lr * 32 + c1] = *(const uint4*)&g_Vth[gb];
            *(uint4*)&Vh[lr * 32 + c2] = *(const uint4*)&g_Vth[gb + 4];
            *(uint4*)&Vl[lr * 32 + c1] = *(const uint4*)&g_Vtl[gb];
            *(uint4*)&Vl[lr * 32 + c2] = *(const uint4*)&g_Vtl[gb + 4];
        }
        if (tid < 16)
            *(float4*)&msk[tid * 4] =
                *(const float4*)(mask + (size_t)b * Sq + c0 + tid * 4);
        __syncthreads();

        // ---- S = Q @ K^T ----
        float s[8][4];
#pragma unroll
        for (int na = 0; na < 8; ++na)
#pragma unroll
            for (int e = 0; e < 4; ++e) s[na][e] = 0.0f;

#pragma unroll
        for (int ks = 0; ks < 4; ++ks) {
            uint32_t ah[4] = {qh[0][2 * ks], qh[1][2 * ks],
                              qh[0][2 * ks + 1], qh[1][2 * ks + 1]};
            uint32_t al[4] = {ql[0][2 * ks], ql[1][2 * ks],
                              ql[0][2 * ks + 1], ql[1][2 * ks + 1]};
            const int wq = (8 * ks + tig) ^ g4;
#pragma unroll
            for (int na = 0; na < 8; ++na) {
                int cb = (na * 8 + g) * 32;
                uint32_t bh[2] = {Kh[cb + wq], Kh[cb + (wq ^ 4)]};
                uint32_t bl[2] = {Kl[cb + wq], Kl[cb + (wq ^ 4)]};
                mma_bf16(s[na], ah, bh);
                mma_bf16(s[na], al, bh);
                mma_bf16(s[na], ah, bl);
            }
        }

        // ---- mask + online softmax ----
#pragma unroll
        for (int na = 0; na < 8; ++na) {
            float m0 = msk[na * 8 + 2 * tig];
            float m1 = msk[na * 8 + 2 * tig + 1];
            s[na][0] += m0; s[na][1] += m1;
            s[na][2] += m0; s[na][3] += m1;
        }

        float mx0 = -1e30f, mx1 = -1e30f;
#pragma unroll
        for (int na = 0; na < 8; ++na) {
            mx0 = fmaxf(mx0, fmaxf(s[na][0], s[na][1]));
            mx1 = fmaxf(mx1, fmaxf(s[na][2], s[na][3]));
        }
        mx0 = fmaxf(mx0, __shfl_xor_sync(0xffffffffu, mx0, 1));
        mx0 = fmaxf(mx0, __shfl_xor_sync(0xffffffffu, mx0, 2));
        mx1 = fmaxf(mx1, __shfl_xor_sync(0xffffffffu, mx1, 1));
        mx1 = fmaxf(mx1, __shfl_xor_sync(0xffffffffu, mx1, 2));

        float mn0 = fmaxf(mrow[0], mx0);
        float mn1 = fmaxf(mrow[1], mx1);
        float fac0 = __expf(mrow[0] - mn0);
        float fac1 = __expf(mrow[1] - mn1);
        mrow[0] = mn0; mrow[1] = mn1;

        float sum0 = 0.0f, sum1 = 0.0f;
#pragma unroll
        for (int na = 0; na < 8; ++na) {
            s[na][0] = __expf(s[na][0] - mn0); sum0 += s[na][0];
            s[na][1] = __expf(s[na][1] - mn0); sum0 += s[na][1];
            s[na][2] = __expf(s[na][2] - mn1); sum1 += s[na][2];
            s[na][3] = __expf(s[na][3] - mn1); sum1 += s[na][3];
        }
        sum0 += __shfl_xor_sync(0xffffffffu, sum0, 1);
        sum0 += __shfl_xor_sync(0xffffffffu, sum0, 2);
        sum1 += __shfl_xor_sync(0xffffffffu, sum1, 1);
        sum1 += __shfl_xor_sync(0xffffffffu, sum1, 2);
        lrow[0] = lrow[0] * fac0 + sum0;
        lrow[1] = lrow[1] * fac1 + sum1;

#pragma unroll
        for (int na = 0; na < 8; ++na) {
            o[na][0] *= fac0; o[na][1] *= fac0;
            o[na][2] *= fac1; o[na][3] *= fac1;
        }

        // ---- pack P into registers ----
        uint32_t ph[2][8], pl[2][8];
#pragma unroll
        for (int na = 0; na < 8; ++na) {
            uint32_t h0 = bf16x2_pack(s[na][1], s[na][0]);
            float r0 = s[na][0] - bfu_lo(h0);
            float r1 = s[na][1] - bfu_hi(h0);
            ph[0][na] = h0;
            pl[0][na] = bf16x2_pack(r1, r0);
            uint32_t h1 = bf16x2_pack(s[na][3], s[na][2]);
            float r2 = s[na][2] - bfu_lo(h1);
            float r3 = s[na][3] - bfu_hi(h1);
            ph[1][na] = h1;
            pl[1][na] = bf16x2_pack(r3, r2);
        }

        // ---- O += P @ V ----
#pragma unroll
        for (int ks = 0; ks < 4; ++ks) {
            uint32_t ah[4] = {ph[0][2 * ks], ph[1][2 * ks],
                              ph[0][2 * ks + 1], ph[1][2 * ks + 1]};
            uint32_t al[4] = {pl[0][2 * ks], pl[1][2 * ks],
                              pl[0][2 * ks + 1], pl[1][2 * ks + 1]};
            const int wv = (8 * ks + tig) ^ g4;
#pragma unroll
            for (int na = 0; na < 8; ++na) {
                int db = (na * 8 + g) * 32;
                uint32_t vh[2] = {Vh[db + wv], Vh[db + (wv ^ 4)]};
                uint32_t vl[2] = {Vl[db + wv], Vl[db + (wv ^ 4)]};
                mma_bf16(o[na], ah, vh);
                mma_bf16(o[na], al, vh);
                mma_bf16(o[na], ah, vl);
            }
        }
        __syncthreads();
    }

    // Epilogue: normalize and emit packed bf16 hi/lo planes
    float i0 = 1.0f / lrow[0];
    float i1 = 1.0f / lrow[1];
    const size_t rb0 = (((size_t)(b * Sq + q0 + R)  * Hq) + ho) >> 1;
    const size_t rb1 = (((size_t)(b * Sq + q0 + R8) * Hq) + ho) >> 1;
#pragma unroll
    for (int na = 0; na < 8; ++na) {
        int w = na * 4 + tig;
        float v0 = o[na][0] * i0, v1 = o[na][1] * i0;
        uint32_t hw = bf16x2_pack(v1, v0);
        g_Aph[rb0 + w] = hw;
        g_Apl[rb0 + w] = bf16x2_pack(v1 - bfu_hi(hw), v0 - bfu_lo(hw));
        float v2 = o[na][2] * i1, v3 = o[na][3] * i1;
        uint32_t hw2 = bf16x2_pack(v3, v2);
        g_Aph[rb1 + w] = hw2;
        g_Apl[rb1 + w] = bf16x2_pack(v3 - bfu_hi(hw2), v2 - bfu_lo(hw2));
    }
}

// ---------------------------------------------------------------------------
// Launch
// ---------------------------------------------------------------------------
extern "C" void kernel_launch(void* const* d_in, const int* in_sizes, int n_in,
                              void* d_out, int out_size) {
    const float* X    = (const float*)d_in[0];
    const float* mask = (const float*)d_in[1];
    const float* cs   = (const float*)d_in[2];
    const float* sn   = (const float*)d_in[3];
    float* out = (float*)d_out;

    float *Qp, *Kp, *Vp;
    uint32_t *Xh, *Xl, *Kph, *Kpl;
    cudaGetSymbolAddress((void**)&Qp, g_Q);
    cudaGetSymbolAddress((void**)&Kp, g_K);
    cudaGetSymbolAddress((void**)&Vp, g_V);
    cudaGetSymbolAddress((void**)&Xh, g_Xh);
    cudaGetSymbolAddress((void**)&Xl, g_Xl);
    cudaGetSymbolAddress((void**)&Kph, g_Kph);
    cudaGetSymbolAddress((void**)&Kpl, g_Kpl);

    const int M = Bq * Sq;                             // 4096
    const size_t shm_g = 4u * GP * sizeof(uint32_t);   // 32,768

    // Pre-pass: weights and X
    const int nw4 = Hq * Hq / 4;
    split_w_bf16<<<dim3(nw4 / 256, 4), 256>>>(
        (const float4*)d_in[4], (const float4*)d_in[5],
        (const float4*)d_in[6], (const float4*)d_in[7], nw4);
    const int nx4 = Bq * Sq * Hq / 4;
    split_pack<<<nx4 / 256, 256>>>((const float4*)X, (uint2*)Xh, (uint2*)Xl,
                                   nx4);

    // QKV projection (fused)
    gemm_bf3_qkv<<<dim3(48, M / 128), 256, shm_g>>>(Qp, Kp, Vp);

    const int PAIRS = Bq * Sq * NHq * (HDq / 2);
    rope_kernel<<<(2 * PAIRS + 255) / 256, 256>>>(Qp, Kp, cs, sn);

    // Pack K (post-rope) and transpose-pack V
    split_pack<<<nx4 / 256, 256>>>((const float4*)Kp, (uint2*)Kph,
                                   (uint2*)Kpl, nx4);
    vtrans_pack<<<dim3(Sq / 64, Bq * NHq), 256>>>(Vp);

    attn_bf16<<<dim3(Sq / 128, NHq, Bq), 256>>>(Qp, mask);

    gemm_bf3_o<<<dim3(Hq / 128, M / 128), 256, shm_g>>>(out);
}

// round 15
// speedup vs baseline: 1.0361x; 1.0361x over previous
#include <cuda_runtime.h>
#include <cuda_bf16.h>
#include <cstddef>
#include <cstdint>

// Problem constants
#define Bq  2
#define Sq  2048
#define Hq  2048
#define NHq 32
#define HDq 64

// fp32 scratch
__device__ float    g_Q[Bq * Sq * Hq];
__device__ float    g_K[Bq * Sq * Hq];
__device__ float    g_V[Bq * Sq * Hq];
// Packed bf16 hi/lo planes (2 bf16 per uint32, packed along K/k-dim)
__device__ uint32_t g_Wh[4][Hq * Hq / 2];
__device__ uint32_t g_Wl[4][Hq * Hq / 2];
__device__ uint32_t g_Xh[Bq * Sq * Hq / 2];
__device__ uint32_t g_Xl[Bq * Sq * Hq / 2];
__device__ uint32_t g_Kph[Bq * Sq * Hq / 2];
__device__ uint32_t g_Kpl[Bq * Sq * Hq / 2];
// V transposed-packed: [(b*NH+h)*64 + d][Sq/2] words, word = (V[2s],V[2s+1])
__device__ uint32_t g_Vth[Bq * NHq * HDq * Sq / 2];
__device__ uint32_t g_Vtl[Bq * NHq * HDq * Sq / 2];
// Attention output packed planes [m][Hq/2]
__device__ uint32_t g_Aph[Bq * Sq * Hq / 2];
__device__ uint32_t g_Apl[Bq * Sq * Hq / 2];

// ---------------------------------------------------------------------------
// Helpers
// ---------------------------------------------------------------------------
__device__ __forceinline__ uint32_t smem_to_u32(const void* smem_ptr) {
    uint32_t addr;
    asm("{ .reg .u64 tmp; cvta.to.shared.u64 tmp, %1; cvt.u32.u64 %0, tmp; }"
        : "=r"(addr) : "l"(smem_ptr));
    return addr;
}

__device__ __forceinline__ uint32_t bf16x2_pack(float hi_elem, float lo_elem) {
    uint32_t r;
    asm("cvt.rn.bf16x2.f32 %0, %1, %2;" : "=r"(r) : "f"(hi_elem), "f"(lo_elem));
    return r;
}
__device__ __forceinline__ float bfu_lo(uint32_t w) {
    return __uint_as_float(w << 16);
}
__device__ __forceinline__ float bfu_hi(uint32_t w) {
    return __uint_as_float(w & 0xFFFF0000u);
}

__device__ __forceinline__ void mma_bf16(float c[4], const uint32_t a[4],
                                         const uint32_t b[2]) {
    asm volatile(
        "mma.sync.aligned.m16n8k16.row.col.f32.bf16.bf16.f32 "
        "{%0,%1,%2,%3}, {%4,%5,%6,%7}, {%8,%9}, {%0,%1,%2,%3};\n"
        : "+f"(c[0]), "+f"(c[1]), "+f"(c[2]), "+f"(c[3])
        : "r"(a[0]), "r"(a[1]), "r"(a[2]), "r"(a[3]), "r"(b[0]), "r"(b[1]));
}

#define FROT(m) ((((m) >> 1) & 3) << 2)

#define CP_ASYNC16(dst_u32, src_ptr) \
    asm volatile("cp.async.cg.shared.global [%0], [%1], 16;" \
                 :: "r"(dst_u32), "l"(src_ptr) : "memory")
#define CP_COMMIT() asm volatile("cp.async.commit_group;" ::: "memory")
#define CP_WAIT0()  asm volatile("cp.async.wait_group 0;" ::: "memory")

// ---------------------------------------------------------------------------
// Pre-pass: split fp32 -> packed bf16 hi/lo planes.
// ---------------------------------------------------------------------------
__device__ __forceinline__ void split4(float4 v, uint2& h, uint2& l) {
    uint32_t h0 = bf16x2_pack(v.y, v.x);
    uint32_t h1 = bf16x2_pack(v.w, v.z);
    float r0 = v.x - bfu_lo(h0);
    float r1 = v.y - bfu_hi(h0);
    float r2 = v.z - bfu_lo(h1);
    float r3 = v.w - bfu_hi(h1);
    h = make_uint2(h0, h1);
    l = make_uint2(bf16x2_pack(r1, r0), bf16x2_pack(r3, r2));
}

__global__ void split_pack(const float4* __restrict__ src,
                           uint2* __restrict__ dh, uint2* __restrict__ dl,
                           int n4) {
    int i = blockIdx.x * blockDim.x + threadIdx.x;
    if (i >= n4) return;
    uint2 h, l;
    split4(src[i], h, l);
    dh[i] = h;
    dl[i] = l;
}

__global__ void split_w_bf16(const float4* __restrict__ w0,
                             const float4* __restrict__ w1,
                             const float4* __restrict__ w2,
                             const float4* __restrict__ w3, int n4) {
    int i = blockIdx.x * blockDim.x + threadIdx.x;
    if (i >= n4) return;
    const float4* s = (blockIdx.y == 0) ? w0 : (blockIdx.y == 1) ? w1
                      : (blockIdx.y == 2) ? w2 : w3;
    uint2 h, l;
    split4(s[i], h, l);
    ((uint2*)g_Wh[blockIdx.y])[i] = h;
    ((uint2*)g_Wl[blockIdx.y])[i] = l;
}

// ---------------------------------------------------------------------------
// V transpose-pack: per (b,h) 64-row tile, write [d][s/2] packed planes.
// ---------------------------------------------------------------------------
__global__ void vtrans_pack(const float* __restrict__ V) {
    __shared__ float vt[64][65];
    const int tid = threadIdx.x;
    const int bh  = blockIdx.y;
    const int b   = bh >> 5;
    const int h   = bh & 31;
    const int s0  = blockIdx.x * 64;

    const float* Vb = V + (size_t)(b * Sq + s0) * Hq + h * 64;
#pragma unroll
    for (int it = 0; it < 4; ++it) {
        int f = tid + it * 256;
        int s = f >> 4, d0 = (f & 15) << 2;
        float4 v = *(const float4*)(Vb + (size_t)s * Hq + d0);
        vt[s][d0] = v.x; vt[s][d0 + 1] = v.y;
        vt[s][d0 + 2] = v.z; vt[s][d0 + 3] = v.w;
    }
    __syncthreads();

    const int d  = tid >> 2;
    const int w0 = (tid & 3) << 3;
    uint32_t hw[8], lw[8];
#pragma unroll
    for (int j = 0; j < 8; ++j) {
        int s2 = w0 + j;
        float a0 = vt[2 * s2][d], a1 = vt[2 * s2 + 1][d];
        uint32_t hv = bf16x2_pack(a1, a0);
        float r0 = a0 - bfu_lo(hv);
        float r1 = a1 - bfu_hi(hv);
        hw[j] = hv;
        lw[j] = bf16x2_pack(r1, r0);
    }
    size_t base = ((size_t)(bh * 64 + d)) * (Sq / 2) + (s0 >> 1) + w0;
    *(uint4*)&g_Vth[base]     = make_uint4(hw[0], hw[1], hw[2], hw[3]);
    *(uint4*)&g_Vth[base + 4] = make_uint4(hw[4], hw[5], hw[6], hw[7]);
    *(uint4*)&g_Vtl[base]     = make_uint4(lw[0], lw[1], lw[2], lw[3]);
    *(uint4*)&g_Vtl[base + 4] = make_uint4(lw[4], lw[5], lw[6], lw[7]);
}

// ---------------------------------------------------------------------------
// bf16 3-mma GEMM (NT), both operands pre-split packed planes (R14, WIN path).
// ---------------------------------------------------------------------------
#define GP 2048   // words per smem plane (128*16)

__device__ __forceinline__ void gemm_bf3_core(uint32_t* sm,
        const uint32_t* __restrict__ Ahg0, const uint32_t* __restrict__ Alg0,
        const uint32_t* __restrict__ Bhg0, const uint32_t* __restrict__ Blg0,
        float* __restrict__ C, int M, int N, int K, int m0, int n0) {
    uint32_t* Ah = sm;
    uint32_t* Al = sm + GP;
    uint32_t* Bh = sm + 2 * GP;
    uint32_t* Bl = sm + 3 * GP;

    const int tid  = threadIdx.x;
    const int lane = tid & 31;
    const int wid  = tid >> 5;
    const int wm   = (wid & 1) * 64;
    const int wn   = (wid >> 1) * 32;
    const int g    = lane >> 2;
    const int tig  = lane & 3;

    const int row = tid >> 1;
    const int hb  = tid & 1;
    const int fr  = FROT(row);
    const int KW  = K >> 1;

    const uint32_t* Ahg = Ahg0 + (size_t)(m0 + row) * KW + 8 * hb;
    const uint32_t* Alg = Alg0 + (size_t)(m0 + row) * KW + 8 * hb;
    const uint32_t* Bhg = Bhg0 + (size_t)(n0 + row) * KW + 8 * hb;
    const uint32_t* Blg = Blg0 + (size_t)(n0 + row) * KW + 8 * hb;

    float acc[4][4][4];
#pragma unroll
    for (int i = 0; i < 4; ++i)
#pragma unroll
        for (int j = 0; j < 4; ++j)
#pragma unroll
            for (int r = 0; r < 4; ++r) acc[i][j][r] = 0.0f;

    uint4 pah[2], pal[2], pbh[2], pbl[2];
#pragma unroll
    for (int v = 0; v < 2; ++v) {
        pah[v] = *(const uint4*)(Ahg + 4 * v);
        pal[v] = *(const uint4*)(Alg + 4 * v);
        pbh[v] = *(const uint4*)(Bhg + 4 * v);
        pbl[v] = *(const uint4*)(Blg + 4 * v);
    }

    const int NCH = K >> 5;
    for (int ch = 0; ch < NCH; ++ch) {
#pragma unroll
        for (int v = 0; v < 2; ++v) {
            int col = (8 * hb + 4 * v) ^ fr;
            *(uint4*)&Ah[row * 16 + col] = pah[v];
            *(uint4*)&Al[row * 16 + col] = pal[v];
            *(uint4*)&Bh[row * 16 + col] = pbh[v];
            *(uint4*)&Bl[row * 16 + col] = pbl[v];
        }
        __syncthreads();

        if (ch + 1 < NCH) {
            const uint32_t* Ahp = Ahg + (size_t)(ch + 1) * 16;
            const uint32_t* Alp = Alg + (size_t)(ch + 1) * 16;
            const uint32_t* Bhp = Bhg + (size_t)(ch + 1) * 16;
            const uint32_t* Blp = Blg + (size_t)(ch + 1) * 16;
#pragma unroll
            for (int v = 0; v < 2; ++v) {
                pah[v] = *(const uint4*)(Ahp + 4 * v);
                pal[v] = *(const uint4*)(Alp + 4 * v);
                pbh[v] = *(const uint4*)(Bhp + 4 * v);
                pbl[v] = *(const uint4*)(Blp + 4 * v);
            }
        }

#pragma unroll
        for (int ks = 0; ks < 2; ++ks) {
            const int kc = tig + 8 * ks;

            uint32_t ah[4][4], al[4][4];
#pragma unroll
            for (int ma = 0; ma < 4; ++ma) {
                int m = wm + ma * 16 + g;
                int off = m * 16 + (kc ^ FROT(m));
                ah[ma][0] = Ah[off];
                ah[ma][1] = Ah[off + 128];
                ah[ma][2] = Ah[off ^ 4];
                ah[ma][3] = Ah[(off ^ 4) + 128];
                al[ma][0] = Al[off];
                al[ma][1] = Al[off + 128];
                al[ma][2] = Al[off ^ 4];
                al[ma][3] = Al[(off ^ 4) + 128];
            }
#pragma unroll
            for (int na = 0; na < 4; ++na) {
                int n = wn + na * 8 + g;
                int offb = n * 16 + (kc ^ FROT(n));
                uint32_t bh[2], bl[2];
                bh[0] = Bh[offb];
                bh[1] = Bh[offb ^ 4];
                bl[0] = Bl[offb];
                bl[1] = Bl[offb ^ 4];
#pragma unroll
                for (int ma = 0; ma < 4; ++ma) {
                    mma_bf16(acc[ma][na], ah[ma], bh);
                    mma_bf16(acc[ma][na], al[ma], bh);
                    mma_bf16(acc[ma][na], ah[ma], bl);
                }
            }
        }
        __syncthreads();
    }

#pragma unroll
    for (int ma = 0; ma < 4; ++ma) {
        int r0 = m0 + wm + ma * 16 + g;
#pragma unroll
        for (int na = 0; na < 4; ++na) {
            int c = n0 + wn + na * 8 + 2 * tig;
            *(float2*)&C[(size_t)r0 * N + c] =
                make_float2(acc[ma][na][0], acc[ma][na][1]);
            *(float2*)&C[(size_t)(r0 + 8) * N + c] =
                make_float2(acc[ma][na][2], acc[ma][na][3]);
        }
    }
}

__global__ void gemm_bf3_o(float* __restrict__ C) {
    extern __shared__ uint32_t smg[];
    gemm_bf3_core(smg, g_Aph, g_Apl, g_Wh[3], g_Wl[3], C, Bq * Sq, Hq, Hq,
                  blockIdx.y * 128, blockIdx.x * 128);
}

__global__ void gemm_bf3_qkv(float* __restrict__ Qo, float* __restrict__ Ko,
                             float* __restrict__ Vo) {
    extern __shared__ uint32_t smg[];
    const int which = blockIdx.x >> 4;
    float* C = (which == 0) ? Qo : (which == 1) ? Ko : Vo;
    gemm_bf3_core(smg, g_Xh, g_Xl, g_Wh[which], g_Wl[which], C,
                  Bq * Sq, Hq, Hq, blockIdx.y * 128, (blockIdx.x & 15) * 128);
}

// ---------------------------------------------------------------------------
// RoPE for Q (in-place fp32, folded 1/8 scale).
// ---------------------------------------------------------------------------
__global__ void rope_q_kernel(float* __restrict__ Q,
                              const float* __restrict__ cs,
                              const float* __restrict__ sn) {
    const int PAIRS = Bq * Sq * NHq * (HDq / 2);
    int p = blockIdx.x * blockDim.x + threadIdx.x;
    if (p >= PAIRS) return;
    int d = p & 31;
    int h = (p >> 5) & 31;
    int s = (p >> 10) & 2047;
    int b = p >> 21;

    size_t base = ((size_t)(b * Sq + s) * Hq) + (size_t)h * HDq + d;
    float c1 = cs[s * HDq + d],      s1 = sn[s * HDq + d];
    float c2 = cs[s * HDq + d + 32], s2 = sn[s * HDq + d + 32];
    float x1 = Q[base];
    float x2 = Q[base + 32];
    Q[base]      = (x1 * c1 - x2 * s1) * 0.125f;
    Q[base + 32] = (x2 * c2 + x1 * s2) * 0.125f;
}

// ---------------------------------------------------------------------------
// RoPE for K fused with bf16 split+pack: reads fp32 K, writes packed planes.
// Thread handles word-pair d2: elements (2d2, 2d2+1) and (2d2+32, 2d2+33).
// ---------------------------------------------------------------------------
__global__ void rope_k_pack(const float* __restrict__ K,
                            const float* __restrict__ cs,
                            const float* __restrict__ sn) {
    const int NK = Bq * Sq * NHq * 16;
    int p = blockIdx.x * blockDim.x + threadIdx.x;
    if (p >= NK) return;
    int d2 = p & 15;
    int h  = (p >> 4) & 31;
    int s  = (p >> 9) & 2047;
    int b  = p >> 20;

    size_t base = ((size_t)(b * Sq + s) * Hq) + (size_t)h * HDq + 2 * d2;
    float2 xa = *(const float2*)(K + base);
    float2 xb = *(const float2*)(K + base + 32);
    float2 ca = *(const float2*)(cs + s * HDq + 2 * d2);
    float2 cb = *(const float2*)(cs + s * HDq + 2 * d2 + 32);
    float2 sa = *(const float2*)(sn + s * HDq + 2 * d2);
    float2 sb = *(const float2*)(sn + s * HDq + 2 * d2 + 32);

    float y0 = xa.x * ca.x - xb.x * sa.x;
    float y1 = xa.y * ca.y - xb.y * sa.y;
    float y2 = xb.x * cb.x + xa.x * sb.x;
    float y3 = xb.y * cb.y + xa.y * sb.y;

    size_t wb = base >> 1;  // word base (base is even)
    uint32_t h0 = bf16x2_pack(y1, y0);
    g_Kph[wb + 0] = h0;
    g_Kpl[wb + 0] = bf16x2_pack(y1 - bfu_hi(h0), y0 - bfu_lo(h0));
    uint32_t h1 = bf16x2_pack(y3, y2);
    g_Kph[wb + 16] = h1;
    g_Kpl[wb + 16] = bf16x2_pack(y3 - bfu_hi(h1), y2 - bfu_lo(h1));
}

// ---------------------------------------------------------------------------
// Flash attention, bf16 3-mma; K/V pre-packed planes, Q in regs, P in regs.
// Double-buffered smem via cp.async: the copy of tile t+1 overlaps the full
// compute of tile t; ONE __syncthreads per tile.
// Dynamic smem: 2 stages x (Kh,Kl,Vh,Vl)[2048] + 2 x msk[64] = 66,048 B.
// ---------------------------------------------------------------------------
#define AST 8192              // words per stage
#define AMSK 16384            // msk offset (words)
#define ATTN_SMEM ((16384 + 128) * 4)

__global__ __launch_bounds__(256, 2)
void attn_bf16(const float* __restrict__ Q, const float* __restrict__ mask) {
    extern __shared__ uint32_t sma[];
    const uint32_t smb = smem_to_u32(sma);

    const int tid  = threadIdx.x;
    const int lane = tid & 31;
    const int wid  = tid >> 5;
    const int g    = lane >> 2;
    const int tig  = lane & 3;
    const int R    = wid * 16 + g;
    const int R8   = R + 8;
    const int g4   = g << 2;

    const int b  = blockIdx.z;
    const int h  = blockIdx.y;
    const int q0 = blockIdx.x * 128;
    const size_t ho = (size_t)h * HDq;

    // Loader indices
    const int lr = tid >> 2;             // 0..63
    const int w0 = (tid & 3) << 3;       // 0,8,16,24
    const int lrot = (lr & 7) << 2;
    const int cA = (w0 ^ lrot);
    const int cB = ((w0 + 4) ^ lrot);
    const size_t kgrow = (((size_t)(b * Sq + lr) * Hq) + ho) >> 1;  // + c0*1024
    const size_t vgrow = ((size_t)((b * NHq + h) * HDq + lr)) * (Sq / 2) + w0;

    // Issue cp.async copies for one tile into a stage
    auto issue_tile = [&](int stage, int t) {
        const int c0 = t * 64;
        uint32_t sb = smb + (uint32_t)(stage * AST) * 4u;
        uint32_t dk = sb + (uint32_t)(lr * 32) * 4u;
        size_t gk = kgrow + (size_t)c0 * 1024;
        CP_ASYNC16(dk + cA * 4,                 g_Kph + gk + w0);
        CP_ASYNC16(dk + cB * 4,                 g_Kph + gk + w0 + 4);
        CP_ASYNC16(dk + (2048 + cA) * 4,        g_Kpl + gk + w0);
        CP_ASYNC16(dk + (2048 + cB) * 4,        g_Kpl + gk + w0 + 4);
        size_t gv = vgrow + (size_t)(c0 >> 1);
        CP_ASYNC16(dk + (4096 + cA) * 4,        g_Vth + gv);
        CP_ASYNC16(dk + (4096 + cB) * 4,        g_Vth + gv + 4);
        CP_ASYNC16(dk + (6144 + cA) * 4,        g_Vtl + gv);
        CP_ASYNC16(dk + (6144 + cB) * 4,        g_Vtl + gv + 4);
        if (tid < 16)
            CP_ASYNC16(smb + (uint32_t)(AMSK + stage * 64 + tid * 4) * 4u,
                       mask + (size_t)b * Sq + c0 + tid * 4);
    };

    // Prologue: start tile 0 copy, then load Q into registers (overlapped)
    issue_tile(0, 0);
    CP_COMMIT();

    uint32_t qh[2][8], ql[2][8];
    {
        const float* Qb = Q + ((size_t)(b * Sq + q0) * Hq) + ho;
#pragma unroll
        for (int rr = 0; rr < 2; ++rr) {
            const float* Qr = Qb + (size_t)(rr ? R8 : R) * Hq + 2 * tig;
#pragma unroll
            for (int u = 0; u < 8; ++u) {
                float2 q = *(const float2*)(Qr + 8 * u);
                uint32_t hw = bf16x2_pack(q.y, q.x);
                float r0 = q.x - bfu_lo(hw);
                float r1 = q.y - bfu_hi(hw);
                qh[rr][u] = hw;
                ql[rr][u] = bf16x2_pack(r1, r0);
            }
        }
    }

    float o[8][4];
#pragma unroll
    for (int na = 0; na < 8; ++na)
#pragma unroll
        for (int e = 0; e < 4; ++e) o[na][e] = 0.0f;
    float mrow[2] = {-1e30f, -1e30f};
    float lrow[2] = {0.0f, 0.0f};

    for (int t = 0; t < Sq / 64; ++t) {
        const int s = t & 1;
        CP_WAIT0();
        __syncthreads();
        if (t + 1 < Sq / 64) {
            issue_tile(s ^ 1, t + 1);
            CP_COMMIT();
        }

        const uint32_t* Kh = sma + s * AST;
        const uint32_t* Kl = Kh + 2048;
        const uint32_t* Vh = Kh + 4096;
        const uint32_t* Vl = Kh + 6144;
        const float* msk = (const float*)(sma + AMSK + s * 64);

        // ---- S = Q @ K^T ----
        float sc[8][4];
#pragma unroll
        for (int na = 0; na < 8; ++na)
#pragma unroll
            for (int e = 0; e < 4; ++e) sc[na][e] = 0.0f;

#pragma unroll
        for (int ks = 0; ks < 4; ++ks) {
            uint32_t ah[4] = {qh[0][2 * ks], qh[1][2 * ks],
                              qh[0][2 * ks + 1], qh[1][2 * ks + 1]};
            uint32_t al[4] = {ql[0][2 * ks], ql[1][2 * ks],
                              ql[0][2 * ks + 1], ql[1][2 * ks + 1]};
            const int wq = (8 * ks + tig) ^ g4;
#pragma unroll
            for (int na = 0; na < 8; ++na) {
                int cb = (na * 8 + g) * 32;
                uint32_t bh[2] = {Kh[cb + wq], Kh[cb + (wq ^ 4)]};
                uint32_t bl[2] = {Kl[cb + wq], Kl[cb + (wq ^ 4)]};
                mma_bf16(sc[na], ah, bh);
                mma_bf16(sc[na], al, bh);
                mma_bf16(sc[na], ah, bl);
            }
        }

        // ---- mask + online softmax ----
#pragma unroll
        for (int na = 0; na < 8; ++na) {
            float m0 = msk[na * 8 + 2 * tig];
            float m1 = msk[na * 8 + 2 * tig + 1];
            sc[na][0] += m0; sc[na][1] += m1;
            sc[na][2] += m0; sc[na][3] += m1;
        }

        float mx0 = -1e30f, mx1 = -1e30f;
#pragma unroll
        for (int na = 0; na < 8; ++na) {
            mx0 = fmaxf(mx0, fmaxf(sc[na][0], sc[na][1]));
            mx1 = fmaxf(mx1, fmaxf(sc[na][2], sc[na][3]));
        }
        mx0 = fmaxf(mx0, __shfl_xor_sync(0xffffffffu, mx0, 1));
        mx0 = fmaxf(mx0, __shfl_xor_sync(0xffffffffu, mx0, 2));
        mx1 = fmaxf(mx1, __shfl_xor_sync(0xffffffffu, mx1, 1));
        mx1 = fmaxf(mx1, __shfl_xor_sync(0xffffffffu, mx1, 2));

        float mn0 = fmaxf(mrow[0], mx0);
        float mn1 = fmaxf(mrow[1], mx1);
        float fac0 = __expf(mrow[0] - mn0);
        float fac1 = __expf(mrow[1] - mn1);
        mrow[0] = mn0; mrow[1] = mn1;

        float sum0 = 0.0f, sum1 = 0.0f;
#pragma unroll
        for (int na = 0; na < 8; ++na) {
            sc[na][0] = __expf(sc[na][0] - mn0); sum0 += sc[na][0];
            sc[na][1] = __expf(sc[na][1] - mn0); sum0 += sc[na][1];
            sc[na][2] = __expf(sc[na][2] - mn1); sum1 += sc[na][2];
            sc[na][3] = __expf(sc[na][3] - mn1); sum1 += sc[na][3];
        }
        sum0 += __shfl_xor_sync(0xffffffffu, sum0, 1);
        sum0 += __shfl_xor_sync(0xffffffffu, sum0, 2);
        sum1 += __shfl_xor_sync(0xffffffffu, sum1, 1);
        sum1 += __shfl_xor_sync(0xffffffffu, sum1, 2);
        lrow[0] = lrow[0] * fac0 + sum0;
        lrow[1] = lrow[1] * fac1 + sum1;

#pragma unroll
        for (int na = 0; na < 8; ++na) {
            o[na][0] *= fac0; o[na][1] *= fac0;
            o[na][2] *= fac1; o[na][3] *= fac1;
        }

        // ---- pack P into registers ----
        uint32_t ph[2][8], pl[2][8];
#pragma unroll
        for (int na = 0; na < 8; ++na) {
            uint32_t h0 = bf16x2_pack(sc[na][1], sc[na][0]);
            float r0 = sc[na][0] - bfu_lo(h0);
            float r1 = sc[na][1] - bfu_hi(h0);
            ph[0][na] = h0;
            pl[0][na] = bf16x2_pack(r1, r0);
            uint32_t h1 = bf16x2_pack(sc[na][3], sc[na][2]);
            float r2 = sc[na][2] - bfu_lo(h1);
            float r3 = sc[na][3] - bfu_hi(h1);
            ph[1][na] = h1;
            pl[1][na] = bf16x2_pack(r3, r2);
        }

        // ---- O += P @ V ----
#pragma unroll
        for (int ks = 0; ks < 4; ++ks) {
            uint32_t ah[4] = {ph[0][2 * ks], ph[1][2 * ks],
                              ph[0][2 * ks + 1], ph[1][2 * ks + 1]};
            uint32_t al[4] = {pl[0][2 * ks], pl[1][2 * ks],
                              pl[0][2 * ks + 1], pl[1][2 * ks + 1]};
            const int wv = (8 * ks + tig) ^ g4;
#pragma unroll
            for (int na = 0; na < 8; ++na) {
                int db = (na * 8 + g) * 32;
                uint32_t vh[2] = {Vh[db + wv], Vh[db + (wv ^ 4)]};
                uint32_t vl[2] = {Vl[db + wv], Vl[db + (wv ^ 4)]};
                mma_bf16(o[na], ah, vh);
                mma_bf16(o[na], al, vh);
                mma_bf16(o[na], ah, vl);
            }
        }
    }

    // Epilogue: normalize and emit packed bf16 hi/lo planes
    float i0 = 1.0f / lrow[0];
    float i1 = 1.0f / lrow[1];
    const size_t rb0 = (((size_t)(b * Sq + q0 + R)  * Hq) + ho) >> 1;
    const size_t rb1 = (((size_t)(b * Sq + q0 + R8) * Hq) + ho) >> 1;
#pragma unroll
    for (int na = 0; na < 8; ++na) {
        int w = na * 4 + tig;
        float v0 = o[na][0] * i0, v1 = o[na][1] * i0;
        uint32_t hw = bf16x2_pack(v1, v0);
        g_Aph[rb0 + w] = hw;
        g_Apl[rb0 + w] = bf16x2_pack(v1 - bfu_hi(hw), v0 - bfu_lo(hw));
        float v2 = o[na][2] * i1, v3 = o[na][3] * i1;
        uint32_t hw2 = bf16x2_pack(v3, v2);
        g_Aph[rb1 + w] = hw2;
        g_Apl[rb1 + w] = bf16x2_pack(v3 - bfu_hi(hw2), v2 - bfu_lo(hw2));
    }
}

// ---------------------------------------------------------------------------
// Launch
// ---------------------------------------------------------------------------
extern "C" void kernel_launch(void* const* d_in, const int* in_sizes, int n_in,
                              void* d_out, int out_size) {
    const float* X    = (const float*)d_in[0];
    const float* mask = (const float*)d_in[1];
    const float* cs   = (const float*)d_in[2];
    const float* sn   = (const float*)d_in[3];
    float* out = (float*)d_out;

    float *Qp, *Kp, *Vp;
    uint32_t *Xh, *Xl;
    cudaGetSymbolAddress((void**)&Qp, g_Q);
    cudaGetSymbolAddress((void**)&Kp, g_K);
    cudaGetSymbolAddress((void**)&Vp, g_V);
    cudaGetSymbolAddress((void**)&Xh, g_Xh);
    cudaGetSymbolAddress((void**)&Xl, g_Xl);

    const int M = Bq * Sq;                             // 4096
    const size_t shm_g = 4u * GP * sizeof(uint32_t);   // 32,768

    static bool attr_set = false;
    if (!attr_set) {
        cudaFuncSetAttribute(attn_bf16,
                             cudaFuncAttributeMaxDynamicSharedMemorySize,
                             ATTN_SMEM);
        attr_set = true;
    }

    // Pre-pass: weights and X
    const int nw4 = Hq * Hq / 4;
    split_w_bf16<<<dim3(nw4 / 256, 4), 256>>>(
        (const float4*)d_in[4], (const float4*)d_in[5],
        (const float4*)d_in[6], (const float4*)d_in[7], nw4);
    const int nx4 = Bq * Sq * Hq / 4;
    split_pack<<<nx4 / 256, 256>>>((const float4*)X, (uint2*)Xh, (uint2*)Xl,
                                   nx4);

    // QKV projection (fused)
    gemm_bf3_qkv<<<dim3(48, M / 128), 256, shm_g>>>(Qp, Kp, Vp);

    // RoPE: Q in-place; K fused rotate+split+pack
    const int PAIRS = Bq * Sq * NHq * (HDq / 2);
    rope_q_kernel<<<PAIRS / 256, 256>>>(Qp, cs, sn);
    const int NK = Bq * Sq * NHq * 16;
    rope_k_pack<<<NK / 256, 256>>>(Kp, cs, sn);

    // V transpose-pack
    vtrans_pack<<<dim3(Sq / 64, Bq * NHq), 256>>>(Vp);

    attn_bf16<<<dim3(Sq / 128, NHq, Bq), 256, ATTN_SMEM>>>(Qp, mask);

    gemm_bf3_o<<<dim3(Hq / 128, M / 128), 256, shm_g>>>(out);
}

// round 16
// speedup vs baseline: 1.1529x; 1.1127x over previous
#include <cuda_runtime.h>
#include <cuda_bf16.h>
#include <cstddef>
#include <cstdint>

// Problem constants
#define Bq  2
#define Sq  2048
#define Hq  2048
#define NHq 32
#define HDq 64

// fp32 scratch
__device__ float    g_Q[Bq * Sq * Hq];
__device__ float    g_K[Bq * Sq * Hq];
__device__ float    g_V[Bq * Sq * Hq];
// Packed bf16 hi/lo planes (2 bf16 per uint32, packed along K/k-dim)
__device__ uint32_t g_Wh[4][Hq * Hq / 2];
__device__ uint32_t g_Wl[4][Hq * Hq / 2];
__device__ uint32_t g_Xh[Bq * Sq * Hq / 2];
__device__ uint32_t g_Xl[Bq * Sq * Hq / 2];
__device__ uint32_t g_Kph[Bq * Sq * Hq / 2];
__device__ uint32_t g_Kpl[Bq * Sq * Hq / 2];
// V transposed-packed: [(b*NH+h)*64 + d][Sq/2] words, word = (V[2s],V[2s+1])
__device__ uint32_t g_Vth[Bq * NHq * HDq * Sq / 2];
__device__ uint32_t g_Vtl[Bq * NHq * HDq * Sq / 2];
// Attention output packed planes [m][Hq/2]
__device__ uint32_t g_Aph[Bq * Sq * Hq / 2];
__device__ uint32_t g_Apl[Bq * Sq * Hq / 2];

// ---------------------------------------------------------------------------
// Helpers
// ---------------------------------------------------------------------------
__device__ __forceinline__ uint32_t smem_to_u32(const void* smem_ptr) {
    uint32_t addr;
    asm("{ .reg .u64 tmp; cvta.to.shared.u64 tmp, %1; cvt.u32.u64 %0, tmp; }"
        : "=r"(addr) : "l"(smem_ptr));
    return addr;
}

__device__ __forceinline__ uint32_t bf16x2_pack(float hi_elem, float lo_elem) {
    uint32_t r;
    asm("cvt.rn.bf16x2.f32 %0, %1, %2;" : "=r"(r) : "f"(hi_elem), "f"(lo_elem));
    return r;
}
__device__ __forceinline__ float bfu_lo(uint32_t w) {
    return __uint_as_float(w << 16);
}
__device__ __forceinline__ float bfu_hi(uint32_t w) {
    return __uint_as_float(w & 0xFFFF0000u);
}

__device__ __forceinline__ void mma_bf16(float c[4], const uint32_t a[4],
                                         const uint32_t b[2]) {
    asm volatile(
        "mma.sync.aligned.m16n8k16.row.col.f32.bf16.bf16.f32 "
        "{%0,%1,%2,%3}, {%4,%5,%6,%7}, {%8,%9}, {%0,%1,%2,%3};\n"
        : "+f"(c[0]), "+f"(c[1]), "+f"(c[2]), "+f"(c[3])
        : "r"(a[0]), "r"(a[1]), "r"(a[2]), "r"(a[3]), "r"(b[0]), "r"(b[1]));
}

#define FROT(m) ((((m) >> 1) & 3) << 2)

#define CP_ASYNC16(dst_u32, src_ptr) \
    asm volatile("cp.async.cg.shared.global [%0], [%1], 16;" \
                 :: "r"(dst_u32), "l"(src_ptr) : "memory")
#define CP_COMMIT() asm volatile("cp.async.commit_group;" ::: "memory")
#define CP_WAIT0()  asm volatile("cp.async.wait_group 0;" ::: "memory")

// ---------------------------------------------------------------------------
// Pre-pass: split fp32 -> packed bf16 hi/lo planes.
// ---------------------------------------------------------------------------
__device__ __forceinline__ void split4(float4 v, uint2& h, uint2& l) {
    uint32_t h0 = bf16x2_pack(v.y, v.x);
    uint32_t h1 = bf16x2_pack(v.w, v.z);
    float r0 = v.x - bfu_lo(h0);
    float r1 = v.y - bfu_hi(h0);
    float r2 = v.z - bfu_lo(h1);
    float r3 = v.w - bfu_hi(h1);
    h = make_uint2(h0, h1);
    l = make_uint2(bf16x2_pack(r1, r0), bf16x2_pack(r3, r2));
}

__global__ void split_pack(const float4* __restrict__ src,
                           uint2* __restrict__ dh, uint2* __restrict__ dl,
                           int n4) {
    int i = blockIdx.x * blockDim.x + threadIdx.x;
    if (i >= n4) return;
    uint2 h, l;
    split4(src[i], h, l);
    dh[i] = h;
    dl[i] = l;
}

__global__ void split_w_bf16(const float4* __restrict__ w0,
                             const float4* __restrict__ w1,
                             const float4* __restrict__ w2,
                             const float4* __restrict__ w3, int n4) {
    int i = blockIdx.x * blockDim.x + threadIdx.x;
    if (i >= n4) return;
    const float4* s = (blockIdx.y == 0) ? w0 : (blockIdx.y == 1) ? w1
                      : (blockIdx.y == 2) ? w2 : w3;
    uint2 h, l;
    split4(s[i], h, l);
    ((uint2*)g_Wh[blockIdx.y])[i] = h;
    ((uint2*)g_Wl[blockIdx.y])[i] = l;
}

// ---------------------------------------------------------------------------
// V transpose-pack: per (b,h) 64-row tile, write [d][s/2] packed planes.
// ---------------------------------------------------------------------------
__global__ void vtrans_pack(const float* __restrict__ V) {
    __shared__ float vt[64][65];
    const int tid = threadIdx.x;
    const int bh  = blockIdx.y;
    const int b   = bh >> 5;
    const int h   = bh & 31;
    const int s0  = blockIdx.x * 64;

    const float* Vb = V + (size_t)(b * Sq + s0) * Hq + h * 64;
#pragma unroll
    for (int it = 0; it < 4; ++it) {
        int f = tid + it * 256;
        int s = f >> 4, d0 = (f & 15) << 2;
        float4 v = *(const float4*)(Vb + (size_t)s * Hq + d0);
        vt[s][d0] = v.x; vt[s][d0 + 1] = v.y;
        vt[s][d0 + 2] = v.z; vt[s][d0 + 3] = v.w;
    }
    __syncthreads();

    const int d  = tid >> 2;
    const int w0 = (tid & 3) << 3;
    uint32_t hw[8], lw[8];
#pragma unroll
    for (int j = 0; j < 8; ++j) {
        int s2 = w0 + j;
        float a0 = vt[2 * s2][d], a1 = vt[2 * s2 + 1][d];
        uint32_t hv = bf16x2_pack(a1, a0);
        float r0 = a0 - bfu_lo(hv);
        float r1 = a1 - bfu_hi(hv);
        hw[j] = hv;
        lw[j] = bf16x2_pack(r1, r0);
    }
    size_t base = ((size_t)(bh * 64 + d)) * (Sq / 2) + (s0 >> 1) + w0;
    *(uint4*)&g_Vth[base]     = make_uint4(hw[0], hw[1], hw[2], hw[3]);
    *(uint4*)&g_Vth[base + 4] = make_uint4(hw[4], hw[5], hw[6], hw[7]);
    *(uint4*)&g_Vtl[base]     = make_uint4(lw[0], lw[1], lw[2], lw[3]);
    *(uint4*)&g_Vtl[base + 4] = make_uint4(lw[4], lw[5], lw[6], lw[7]);
}

// ---------------------------------------------------------------------------
// bf16 3-mma GEMM (NT), pre-split packed planes, cp.async double-buffered.
// Loop: wait0 -> sync -> issue(t+1) -> mma(t). One barrier per chunk; the
// copy of chunk t+1 overlaps the entire mma phase of chunk t.
// Dynamic smem: 2 stages x 4 planes x 2048 words = 65,536 B.
// ---------------------------------------------------------------------------
#define GP  2048              // words per smem plane (128*16)
#define GST (4 * GP)          // words per stage
#define GEMM_SMEM (2 * GST * 4)

__device__ __forceinline__ void gemm_bf3_core(uint32_t* sm,
        const uint32_t* __restrict__ Ahg0, const uint32_t* __restrict__ Alg0,
        const uint32_t* __restrict__ Bhg0, const uint32_t* __restrict__ Blg0,
        float* __restrict__ C, int M, int N, int K, int m0, int n0) {
    const int tid  = threadIdx.x;
    const int lane = tid & 31;
    const int wid  = tid >> 5;
    const int wm   = (wid & 1) * 64;
    const int wn   = (wid >> 1) * 32;
    const int g    = lane >> 2;
    const int tig  = lane & 3;

    const int row = tid >> 1;
    const int hb  = tid & 1;
    const int fr  = FROT(row);
    const int KW  = K >> 1;
    const uint32_t smb = smem_to_u32(sm);

    const uint32_t* Ahg = Ahg0 + (size_t)(m0 + row) * KW + 8 * hb;
    const uint32_t* Alg = Alg0 + (size_t)(m0 + row) * KW + 8 * hb;
    const uint32_t* Bhg = Bhg0 + (size_t)(n0 + row) * KW + 8 * hb;
    const uint32_t* Blg = Blg0 + (size_t)(n0 + row) * KW + 8 * hb;

    const int col1 = (8 * hb) ^ fr;
    const int col2 = (8 * hb + 4) ^ fr;

    auto issue = [&](int stage, int ch) {
        const int ko = ch * 16;
        uint32_t dA = smb + (uint32_t)(stage * GST + row * 16) * 4u;
        CP_ASYNC16(dA + col1 * 4,            Ahg + ko);
        CP_ASYNC16(dA + col2 * 4,            Ahg + ko + 4);
        CP_ASYNC16(dA + (GP + col1) * 4,     Alg + ko);
        CP_ASYNC16(dA + (GP + col2) * 4,     Alg + ko + 4);
        CP_ASYNC16(dA + (2 * GP + col1) * 4, Bhg + ko);
        CP_ASYNC16(dA + (2 * GP + col2) * 4, Bhg + ko + 4);
        CP_ASYNC16(dA + (3 * GP + col1) * 4, Blg + ko);
        CP_ASYNC16(dA + (3 * GP + col2) * 4, Blg + ko + 4);
        CP_COMMIT();
    };

    float acc[4][4][4];
#pragma unroll
    for (int i = 0; i < 4; ++i)
#pragma unroll
        for (int j = 0; j < 4; ++j)
#pragma unroll
            for (int r = 0; r < 4; ++r) acc[i][j][r] = 0.0f;

    issue(0, 0);

    const int NCH = K >> 5;
    for (int ch = 0; ch < NCH; ++ch) {
        const int s = ch & 1;
        CP_WAIT0();
        __syncthreads();
        if (ch + 1 < NCH)
            issue(s ^ 1, ch + 1);

        const uint32_t* Ah = sm + s * GST;
        const uint32_t* Al = Ah + GP;
        const uint32_t* Bh = Ah + 2 * GP;
        const uint32_t* Bl = Ah + 3 * GP;

#pragma unroll
        for (int ks = 0; ks < 2; ++ks) {
            const int kc = tig + 8 * ks;

            uint32_t ah[4][4], al[4][4];
#pragma unroll
            for (int ma = 0; ma < 4; ++ma) {
                int m = wm + ma * 16 + g;
                int off = m * 16 + (kc ^ FROT(m));
                ah[ma][0] = Ah[off];
                ah[ma][1] = Ah[off + 128];
                ah[ma][2] = Ah[off ^ 4];
                ah[ma][3] = Ah[(off ^ 4) + 128];
                al[ma][0] = Al[off];
                al[ma][1] = Al[off + 128];
                al[ma][2] = Al[off ^ 4];
                al[ma][3] = Al[(off ^ 4) + 128];
            }
#pragma unroll
            for (int na = 0; na < 4; ++na) {
                int n = wn + na * 8 + g;
                int offb = n * 16 + (kc ^ FROT(n));
                uint32_t bh[2], bl[2];
                bh[0] = Bh[offb];
                bh[1] = Bh[offb ^ 4];
                bl[0] = Bl[offb];
                bl[1] = Bl[offb ^ 4];
#pragma unroll
                for (int ma = 0; ma < 4; ++ma) {
                    mma_bf16(acc[ma][na], ah[ma], bh);
                    mma_bf16(acc[ma][na], al[ma], bh);
                    mma_bf16(acc[ma][na], ah[ma], bl);
                }
            }
        }
    }

#pragma unroll
    for (int ma = 0; ma < 4; ++ma) {
        int r0 = m0 + wm + ma * 16 + g;
#pragma unroll
        for (int na = 0; na < 4; ++na) {
            int c = n0 + wn + na * 8 + 2 * tig;
            *(float2*)&C[(size_t)r0 * N + c] =
                make_float2(acc[ma][na][0], acc[ma][na][1]);
            *(float2*)&C[(size_t)(r0 + 8) * N + c] =
                make_float2(acc[ma][na][2], acc[ma][na][3]);
        }
    }
}

__global__ void gemm_bf3_o(float* __restrict__ C) {
    extern __shared__ uint32_t smg[];
    gemm_bf3_core(smg, g_Aph, g_Apl, g_Wh[3], g_Wl[3], C, Bq * Sq, Hq, Hq,
                  blockIdx.y * 128, blockIdx.x * 128);
}

__global__ void gemm_bf3_qkv(float* __restrict__ Qo, float* __restrict__ Ko,
                             float* __restrict__ Vo) {
    extern __shared__ uint32_t smg[];
    const int which = blockIdx.x >> 4;
    float* C = (which == 0) ? Qo : (which == 1) ? Ko : Vo;
    gemm_bf3_core(smg, g_Xh, g_Xl, g_Wh[which], g_Wl[which], C,
                  Bq * Sq, Hq, Hq, blockIdx.y * 128, (blockIdx.x & 15) * 128);
}

// ---------------------------------------------------------------------------
// RoPE for K fused with bf16 split+pack (R15, validated).
// ---------------------------------------------------------------------------
__global__ void rope_k_pack(const float* __restrict__ K,
                            const float* __restrict__ cs,
                            const float* __restrict__ sn) {
    const int NK = Bq * Sq * NHq * 16;
    int p = blockIdx.x * blockDim.x + threadIdx.x;
    if (p >= NK) return;
    int d2 = p & 15;
    int h  = (p >> 4) & 31;
    int s  = (p >> 9) & 2047;
    int b  = p >> 20;

    size_t base = ((size_t)(b * Sq + s) * Hq) + (size_t)h * HDq + 2 * d2;
    float2 xa = *(const float2*)(K + base);
    float2 xb = *(const float2*)(K + base + 32);
    float2 ca = *(const float2*)(cs + s * HDq + 2 * d2);
    float2 cb = *(const float2*)(cs + s * HDq + 2 * d2 + 32);
    float2 sa = *(const float2*)(sn + s * HDq + 2 * d2);
    float2 sb = *(const float2*)(sn + s * HDq + 2 * d2 + 32);

    float y0 = xa.x * ca.x - xb.x * sa.x;
    float y1 = xa.y * ca.y - xb.y * sa.y;
    float y2 = xb.x * cb.x + xa.x * sb.x;
    float y3 = xb.y * cb.y + xa.y * sb.y;

    size_t wb = base >> 1;
    uint32_t h0 = bf16x2_pack(y1, y0);
    g_Kph[wb + 0] = h0;
    g_Kpl[wb + 0] = bf16x2_pack(y1 - bfu_hi(h0), y0 - bfu_lo(h0));
    uint32_t h1 = bf16x2_pack(y3, y2);
    g_Kph[wb + 16] = h1;
    g_Kpl[wb + 16] = bf16x2_pack(y3 - bfu_hi(h1), y2 - bfu_lo(h1));
}

// ---------------------------------------------------------------------------
// Flash attention (R15 structure) + fused rope-Q at register load.
// Thread owns both d and d+32 for all its columns, so the rotation is
// register-local: no separate rope-Q kernel, no extra Q traffic.
// ---------------------------------------------------------------------------
#define AST 8192              // words per stage
#define AMSK 16384            // msk offset (words)
#define ATTN_SMEM ((16384 + 128) * 4)

__global__ __launch_bounds__(256, 2)
void attn_bf16(const float* __restrict__ Q, const float* __restrict__ mask,
               const float* __restrict__ cs, const float* __restrict__ sn) {
    extern __shared__ uint32_t sma[];
    const uint32_t smb = smem_to_u32(sma);

    const int tid  = threadIdx.x;
    const int lane = tid & 31;
    const int wid  = tid >> 5;
    const int g    = lane >> 2;
    const int tig  = lane & 3;
    const int R    = wid * 16 + g;
    const int R8   = R + 8;
    const int g4   = g << 2;

    const int b  = blockIdx.z;
    const int h  = blockIdx.y;
    const int q0 = blockIdx.x * 128;
    const size_t ho = (size_t)h * HDq;

    // Loader indices
    const int lr = tid >> 2;
    const int w0 = (tid & 3) << 3;
    const int lrot = (lr & 7) << 2;
    const int cA = (w0 ^ lrot);
    const int cB = ((w0 + 4) ^ lrot);
    const size_t kgrow = (((size_t)(b * Sq + lr) * Hq) + ho) >> 1;
    const size_t vgrow = ((size_t)((b * NHq + h) * HDq + lr)) * (Sq / 2) + w0;

    auto issue_tile = [&](int stage, int t) {
        const int c0 = t * 64;
        uint32_t dk = smb + (uint32_t)(stage * AST + lr * 32) * 4u;
        size_t gk = kgrow + (size_t)c0 * 1024;
        CP_ASYNC16(dk + cA * 4,          g_Kph + gk + w0);
        CP_ASYNC16(dk + cB * 4,          g_Kph + gk + w0 + 4);
        CP_ASYNC16(dk + (2048 + cA) * 4, g_Kpl + gk + w0);
        CP_ASYNC16(dk + (2048 + cB) * 4, g_Kpl + gk + w0 + 4);
        size_t gv = vgrow + (size_t)(c0 >> 1);
        CP_ASYNC16(dk + (4096 + cA) * 4, g_Vth + gv);
        CP_ASYNC16(dk + (4096 + cB) * 4, g_Vth + gv + 4);
        CP_ASYNC16(dk + (6144 + cA) * 4, g_Vtl + gv);
        CP_ASYNC16(dk + (6144 + cB) * 4, g_Vtl + gv + 4);
        if (tid < 16)
            CP_ASYNC16(smb + (uint32_t)(AMSK + stage * 64 + tid * 4) * 4u,
                       mask + (size_t)b * Sq + c0 + tid * 4);
    };

    issue_tile(0, 0);
    CP_COMMIT();

    // ---- Q rows -> registers with fused rope + 1/8 scale + bf16 split ----
    uint32_t qh[2][8], ql[2][8];
    {
        const float* Qb = Q + ((size_t)(b * Sq + q0) * Hq) + ho;
#pragma unroll
        for (int rr = 0; rr < 2; ++rr) {
            const int srow = q0 + (rr ? R8 : R);
            const float* Qr = Qb + (size_t)(rr ? R8 : R) * Hq + 2 * tig;
            const float* Cr = cs + (size_t)srow * HDq + 2 * tig;
            const float* Sr = sn + (size_t)srow * HDq + 2 * tig;
            float2 q[8], cc[8], ss[8];
#pragma unroll
            for (int u = 0; u < 8; ++u) {
                q[u]  = *(const float2*)(Qr + 8 * u);
                cc[u] = *(const float2*)(Cr + 8 * u);
                ss[u] = *(const float2*)(Sr + 8 * u);
            }
#pragma unroll
            for (int u = 0; u < 4; ++u) {
                float y0 = (q[u].x * cc[u].x - q[u + 4].x * ss[u].x) * 0.125f;
                float y1 = (q[u].y * cc[u].y - q[u + 4].y * ss[u].y) * 0.125f;
                float y2 = (q[u + 4].x * cc[u + 4].x + q[u].x * ss[u + 4].x) * 0.125f;
                float y3 = (q[u + 4].y * cc[u + 4].y + q[u].y * ss[u + 4].y) * 0.125f;
                uint32_t hw = bf16x2_pack(y1, y0);
                qh[rr][u] = hw;
                ql[rr][u] = bf16x2_pack(y1 - bfu_hi(hw), y0 - bfu_lo(hw));
                uint32_t hw2 = bf16x2_pack(y3, y2);
                qh[rr][u + 4] = hw2;
                ql[rr][u + 4] = bf16x2_pack(y3 - bfu_hi(hw2), y2 - bfu_lo(hw2));
            }
        }
    }

    float o[8][4];
#pragma unroll
    for (int na = 0; na < 8; ++na)
#pragma unroll
        for (int e = 0; e < 4; ++e) o[na][e] = 0.0f;
    float mrow[2] = {-1e30f, -1e30f};
    float lrow[2] = {0.0f, 0.0f};

    for (int t = 0; t < Sq / 64; ++t) {
        const int s = t & 1;
        CP_WAIT0();
        __syncthreads();
        if (t + 1 < Sq / 64) {
            issue_tile(s ^ 1, t + 1);
            CP_COMMIT();
        }

        const uint32_t* Kh = sma + s * AST;
        const uint32_t* Kl = Kh + 2048;
        const uint32_t* Vh = Kh + 4096;
        const uint32_t* Vl = Kh + 6144;
        const float* msk = (const float*)(sma + AMSK + s * 64);

        // ---- S = Q @ K^T ----
        float sc[8][4];
#pragma unroll
        for (int na = 0; na < 8; ++na)
#pragma unroll
            for (int e = 0; e < 4; ++e) sc[na][e] = 0.0f;

#pragma unroll
        for (int ks = 0; ks < 4; ++ks) {
            uint32_t ah[4] = {qh[0][2 * ks], qh[1][2 * ks],
                              qh[0][2 * ks + 1], qh[1][2 * ks + 1]};
            uint32_t al[4] = {ql[0][2 * ks], ql[1][2 * ks],
                              ql[0][2 * ks + 1], ql[1][2 * ks + 1]};
            const int wq = (8 * ks + tig) ^ g4;
#pragma unroll
            for (int na = 0; na < 8; ++na) {
                int cb = (na * 8 + g) * 32;
                uint32_t bh[2] = {Kh[cb + wq], Kh[cb + (wq ^ 4)]};
                uint32_t bl[2] = {Kl[cb + wq], Kl[cb + (wq ^ 4)]};
                mma_bf16(sc[na], ah, bh);
                mma_bf16(sc[na], al, bh);
                mma_bf16(sc[na], ah, bl);
            }
        }

        // ---- mask + online softmax ----
#pragma unroll
        for (int na = 0; na < 8; ++na) {
            float m0 = msk[na * 8 + 2 * tig];
            float m1 = msk[na * 8 + 2 * tig + 1];
            sc[na][0] += m0; sc[na][1] += m1;
            sc[na][2] += m0; sc[na][3] += m1;
        }

        float mx0 = -1e30f, mx1 = -1e30f;
#pragma unroll
        for (int na = 0; na < 8; ++na) {
            mx0 = fmaxf(mx0, fmaxf(sc[na][0], sc[na][1]));
            mx1 = fmaxf(mx1, fmaxf(sc[na][2], sc[na][3]));
        }
        mx0 = fmaxf(mx0, __shfl_xor_sync(0xffffffffu, mx0, 1));
        mx0 = fmaxf(mx0, __shfl_xor_sync(0xffffffffu, mx0, 2));
        mx1 = fmaxf(mx1, __shfl_xor_sync(0xffffffffu, mx1, 1));
        mx1 = fmaxf(mx1, __shfl_xor_sync(0xffffffffu, mx1, 2));

        float mn0 = fmaxf(mrow[0], mx0);
        float mn1 = fmaxf(mrow[1], mx1);
        float fac0 = __expf(mrow[0] - mn0);
        float fac1 = __expf(mrow[1] - mn1);
        mrow[0] = mn0; mrow[1] = mn1;

        float sum0 = 0.0f, sum1 = 0.0f;
#pragma unroll
        for (int na = 0; na < 8; ++na) {
            sc[na][0] = __expf(sc[na][0] - mn0); sum0 += sc[na][0];
            sc[na][1] = __expf(sc[na][1] - mn0); sum0 += sc[na][1];
            sc[na][2] = __expf(sc[na][2] - mn1); sum1 += sc[na][2];
            sc[na][3] = __expf(sc[na][3] - mn1); sum1 += sc[na][3];
        }
        sum0 += __shfl_xor_sync(0xffffffffu, sum0, 1);
        sum0 += __shfl_xor_sync(0xffffffffu, sum0, 2);
        sum1 += __shfl_xor_sync(0xffffffffu, sum1, 1);
        sum1 += __shfl_xor_sync(0xffffffffu, sum1, 2);
        lrow[0] = lrow[0] * fac0 + sum0;
        lrow[1] = lrow[1] * fac1 + sum1;

#pragma unroll
        for (int na = 0; na < 8; ++na) {
            o[na][0] *= fac0; o[na][1] *= fac0;
            o[na][2] *= fac1; o[na][3] *= fac1;
        }

        // ---- pack P into registers ----
        uint32_t ph[2][8], pl[2][8];
#pragma unroll
        for (int na = 0; na < 8; ++na) {
            uint32_t h0 = bf16x2_pack(sc[na][1], sc[na][0]);
            float r0 = sc[na][0] - bfu_lo(h0);
            float r1 = sc[na][1] - bfu_hi(h0);
            ph[0][na] = h0;
            pl[0][na] = bf16x2_pack(r1, r0);
            uint32_t h1 = bf16x2_pack(sc[na][3], sc[na][2]);
            float r2 = sc[na][2] - bfu_lo(h1);
            float r3 = sc[na][3] - bfu_hi(h1);
            ph[1][na] = h1;
            pl[1][na] = bf16x2_pack(r3, r2);
        }

        // ---- O += P @ V ----
#pragma unroll
        for (int ks = 0; ks < 4; ++ks) {
            uint32_t ah[4] = {ph[0][2 * ks], ph[1][2 * ks],
                              ph[0][2 * ks + 1], ph[1][2 * ks + 1]};
            uint32_t al[4] = {pl[0][2 * ks], pl[1][2 * ks],
                              pl[0][2 * ks + 1], pl[1][2 * ks + 1]};
            const int wv = (8 * ks + tig) ^ g4;
#pragma unroll
            for (int na = 0; na < 8; ++na) {
                int db = (na * 8 + g) * 32;
                uint32_t vh[2] = {Vh[db + wv], Vh[db + (wv ^ 4)]};
                uint32_t vl[2] = {Vl[db + wv], Vl[db + (wv ^ 4)]};
                mma_bf16(o[na], ah, vh);
                mma_bf16(o[na], al, vh);
                mma_bf16(o[na], ah, vl);
            }
        }
    }

    // Epilogue: normalize and emit packed bf16 hi/lo planes
    float i0 = 1.0f / lrow[0];
    float i1 = 1.0f / lrow[1];
    const size_t rb0 = (((size_t)(b * Sq + q0 + R)  * Hq) + ho) >> 1;
    const size_t rb1 = (((size_t)(b * Sq + q0 + R8) * Hq) + ho) >> 1;
#pragma unroll
    for (int na = 0; na < 8; ++na) {
        int w = na * 4 + tig;
        float v0 = o[na][0] * i0, v1 = o[na][1] * i0;
        uint32_t hw = bf16x2_pack(v1, v0);
        g_Aph[rb0 + w] = hw;
        g_Apl[rb0 + w] = bf16x2_pack(v1 - bfu_hi(hw), v0 - bfu_lo(hw));
        float v2 = o[na][2] * i1, v3 = o[na][3] * i1;
        uint32_t hw2 = bf16x2_pack(v3, v2);
        g_Aph[rb1 + w] = hw2;
        g_Apl[rb1 + w] = bf16x2_pack(v3 - bfu_hi(hw2), v2 - bfu_lo(hw2));
    }
}

// ---------------------------------------------------------------------------
// Launch
// ---------------------------------------------------------------------------
extern "C" void kernel_launch(void* const* d_in, const int* in_sizes, int n_in,
                              void* d_out, int out_size) {
    const float* X    = (const float*)d_in[0];
    const float* mask = (const float*)d_in[1];
    const float* cs   = (const float*)d_in[2];
    const float* sn   = (const float*)d_in[3];
    float* out = (float*)d_out;

    float *Qp, *Kp, *Vp;
    uint32_t *Xh, *Xl;
    cudaGetSymbolAddress((void**)&Qp, g_Q);
    cudaGetSymbolAddress((void**)&Kp, g_K);
    cudaGetSymbolAddress((void**)&Vp, g_V);
    cudaGetSymbolAddress((void**)&Xh, g_Xh);
    cudaGetSymbolAddress((void**)&Xl, g_Xl);

    const int M = Bq * Sq;                             // 4096

    static bool attr_set = false;
    if (!attr_set) {
        cudaFuncSetAttribute(attn_bf16,
                             cudaFuncAttributeMaxDynamicSharedMemorySize,
                             ATTN_SMEM);
        cudaFuncSetAttribute(gemm_bf3_qkv,
                             cudaFuncAttributeMaxDynamicSharedMemorySize,
                             GEMM_SMEM);
        cudaFuncSetAttribute(gemm_bf3_o,
                             cudaFuncAttributeMaxDynamicSharedMemorySize,
                             GEMM_SMEM);
        attr_set = true;
    }

    // Pre-pass: weights and X
    const int nw4 = Hq * Hq / 4;
    split_w_bf16<<<dim3(nw4 / 256, 4), 256>>>(
        (const float4*)d_in[4], (const float4*)d_in[5],
        (const float4*)d_in[6], (const float4*)d_in[7], nw4);
    const int nx4 = Bq * Sq * Hq / 4;
    split_pack<<<nx4 / 256, 256>>>((const float4*)X, (uint2*)Xh, (uint2*)Xl,
                                   nx4);

    // QKV projection (fused)
    gemm_bf3_qkv<<<dim3(48, M / 128), 256, GEMM_SMEM>>>(Qp, Kp, Vp);

    // K: fused rope + split + pack. (Q rope is fused into attention.)
    const int NK = Bq * Sq * NHq * 16;
    rope_k_pack<<<NK / 256, 256>>>(Kp, cs, sn);

    // V transpose-pack
    vtrans_pack<<<dim3(Sq / 64, Bq * NHq), 256>>>(Vp);

    attn_bf16<<<dim3(Sq / 128, NHq, Bq), 256, ATTN_SMEM>>>(Qp, mask, cs, sn);

    gemm_bf3_o<<<dim3(Hq / 128, M / 128), 256, GEMM_SMEM>>>(out);
}